// round 17
// baseline (speedup 1.0000x reference)
#include <cuda_runtime.h>
#include <cuda_bf16.h>
#include <mma.h>
#include <math.h>
#include <stdint.h>

using namespace nvcuda;

#define BATCH 4
#define TLEN  2048
#define CDIM  2048
#define HS    64
#define NH    32
#define MTOT  (BATCH*TLEN)   /* 8192 */

/* ---------------- scratch (static device allocations; no cudaMalloc) ------- */
__device__ float g_X  [(size_t)MTOT*CDIM];
__device__ float g_XX1[(size_t)MTOT*128];
__device__ float g_XW1[(size_t)MTOT*32];
__device__ float g_T1 [(size_t)MTOT*128];
__device__ float g_DEC[(size_t)MTOT*CDIM];
__device__ float g_R  [(size_t)MTOT*CDIM];
__device__ float g_K  [(size_t)MTOT*CDIM];
__device__ float g_V  [(size_t)MTOT*CDIM];
__device__ float g_V2 [(size_t)MTOT*CDIM];
__device__ float g_Y  [(size_t)MTOT*CDIM];
/* bf16 hi/lo splits */
__device__ __nv_bfloat16 g_XIH[(size_t)MTOT*CDIM];
__device__ __nv_bfloat16 g_XIL[(size_t)MTOT*CDIM];
__device__ __nv_bfloat16 g_XH [(size_t)MTOT*CDIM];
__device__ __nv_bfloat16 g_XL [(size_t)MTOT*CDIM];
__device__ __nv_bfloat16 g_YH [(size_t)MTOT*CDIM];
__device__ __nv_bfloat16 g_YL [(size_t)MTOT*CDIM];
__device__ __nv_bfloat16 g_XWH[(size_t)MTOT*CDIM];
__device__ __nv_bfloat16 g_XWL[(size_t)MTOT*CDIM];
__device__ __nv_bfloat16 g_VWH[(size_t)CDIM*CDIM];
__device__ __nv_bfloat16 g_VWL[(size_t)CDIM*CDIM];
__device__ __nv_bfloat16 g_OWH[(size_t)CDIM*CDIM];
__device__ __nv_bfloat16 g_OWL[(size_t)CDIM*CDIM];
/* transposed weight splits: [N, K] layout */
__device__ __nv_bfloat16 g_W1TH[(size_t)128*CDIM];
__device__ __nv_bfloat16 g_W1TL[(size_t)128*CDIM];
__device__ __nv_bfloat16 g_DW1TH[(size_t)128*CDIM];
__device__ __nv_bfloat16 g_DW1TL[(size_t)128*CDIM];
__device__ __nv_bfloat16 g_WW1TH[(size_t)32*CDIM];
__device__ __nv_bfloat16 g_WW1TL[(size_t)32*CDIM];

#define WLD 40   /* smem row pitch in bf16 */

/* ================= bf16-split WMMA GEMM (NT) — R10-exact core ============== */
__global__ __launch_bounds__(256)
void gemm_wmma3(const __nv_bfloat16* __restrict__ AH, const __nv_bfloat16* __restrict__ AL,
                const __nv_bfloat16* __restrict__ BH, const __nv_bfloat16* __restrict__ BL,
                float* __restrict__ C, int M, int N, int K)
{
    __shared__ __nv_bfloat16 AsH[128][WLD];
    __shared__ __nv_bfloat16 AsL[128][WLD];
    __shared__ __nv_bfloat16 BsH[128][WLD];
    __shared__ __nv_bfloat16 BsL[128][WLD];

    const int tid = threadIdx.x;
    const int wid = tid >> 5;
    const int wm = wid & 1;
    const int wn = wid >> 1;
    const int bm = blockIdx.y * 128;
    const int bn = blockIdx.x * 128;

    wmma::fragment<wmma::accumulator, 16, 16, 16, float> acc[4][2];
#pragma unroll
    for (int i = 0; i < 4; i++)
#pragma unroll
        for (int j = 0; j < 2; j++) wmma::fill_fragment(acc[i][j], 0.f);

    int lrow[2], lc8[2];
#pragma unroll
    for (int u = 0; u < 2; u++) {
        int i = tid + (u << 8);
        lrow[u] = i >> 2;
        lc8[u]  = (i & 3) << 3;
    }

    uint4 pAH[2], pAL[2], pBH[2], pBL[2];
#pragma unroll
    for (int u = 0; u < 2; u++) {
        size_t sa = (size_t)(bm + lrow[u]) * K + lc8[u];
        size_t sb = (size_t)(bn + lrow[u]) * K + lc8[u];
        pAH[u] = *(const uint4*)(AH + sa);
        pAL[u] = *(const uint4*)(AL + sa);
        pBH[u] = *(const uint4*)(BH + sb);
        pBL[u] = *(const uint4*)(BL + sb);
    }

    const int nchunks = K >> 5;
    for (int c = 0; c < nchunks; c++) {
#pragma unroll
        for (int u = 0; u < 2; u++) {
            *(uint4*)&AsH[lrow[u]][lc8[u]] = pAH[u];
            *(uint4*)&AsL[lrow[u]][lc8[u]] = pAL[u];
            *(uint4*)&BsH[lrow[u]][lc8[u]] = pBH[u];
            *(uint4*)&BsL[lrow[u]][lc8[u]] = pBL[u];
        }
        __syncthreads();

        if (c + 1 < nchunks) {
            const int k0 = (c + 1) << 5;
#pragma unroll
            for (int u = 0; u < 2; u++) {
                size_t sa = (size_t)(bm + lrow[u]) * K + k0 + lc8[u];
                size_t sb = (size_t)(bn + lrow[u]) * K + k0 + lc8[u];
                pAH[u] = *(const uint4*)(AH + sa);
                pAL[u] = *(const uint4*)(AL + sa);
                pBH[u] = *(const uint4*)(BH + sb);
                pBL[u] = *(const uint4*)(BL + sb);
            }
        }

#pragma unroll
        for (int ks = 0; ks < 2; ks++) {
            wmma::fragment<wmma::matrix_b, 16, 16, 16, __nv_bfloat16, wmma::col_major> bh[2], bl[2];
#pragma unroll
            for (int j = 0; j < 2; j++) {
                wmma::load_matrix_sync(bh[j], &BsH[wn*32 + j*16][ks*16], WLD);
                wmma::load_matrix_sync(bl[j], &BsL[wn*32 + j*16][ks*16], WLD);
            }
#pragma unroll
            for (int i = 0; i < 4; i++) {
                wmma::fragment<wmma::matrix_a, 16, 16, 16, __nv_bfloat16, wmma::row_major> ah, al;
                wmma::load_matrix_sync(ah, &AsH[wm*64 + i*16][ks*16], WLD);
                wmma::load_matrix_sync(al, &AsL[wm*64 + i*16][ks*16], WLD);
#pragma unroll
                for (int j = 0; j < 2; j++) {
                    wmma::mma_sync(acc[i][j], ah, bh[j], acc[i][j]);
                    wmma::mma_sync(acc[i][j], ah, bl[j], acc[i][j]);
                    wmma::mma_sync(acc[i][j], al, bh[j], acc[i][j]);
                }
            }
        }
        __syncthreads();
    }

#pragma unroll
    for (int i = 0; i < 4; i++)
#pragma unroll
        for (int j = 0; j < 2; j++)
            wmma::store_matrix_sync(&C[(size_t)(bm + wm*64 + i*16) * N + bn + wn*32 + j*16],
                                    acc[i][j], N, wmma::mem_row_major);
}

/* ================= skinny variant: BM=64, BN=128, tanh epilogue ============ */
__global__ __launch_bounds__(256)
void gemm_wmma3_skinny(const __nv_bfloat16* __restrict__ AH, const __nv_bfloat16* __restrict__ AL,
                       const __nv_bfloat16* __restrict__ BH, const __nv_bfloat16* __restrict__ BL,
                       float* __restrict__ C, int M, int K)
{
    __shared__ __nv_bfloat16 AsH[64][WLD];
    __shared__ __nv_bfloat16 AsL[64][WLD];
    __shared__ __nv_bfloat16 BsH[128][WLD];
    __shared__ __nv_bfloat16 BsL[128][WLD];

    const int tid = threadIdx.x;
    const int wid = tid >> 5;
    const int wm = wid & 1;
    const int wn = wid >> 1;
    const int bm = blockIdx.y * 64;

    wmma::fragment<wmma::accumulator, 16, 16, 16, float> acc[2][2];
#pragma unroll
    for (int i = 0; i < 2; i++)
#pragma unroll
        for (int j = 0; j < 2; j++) wmma::fill_fragment(acc[i][j], 0.f);

    const int larA = tid >> 2, lcA = (tid & 3) << 3;
    int lrB[2], lcB[2];
#pragma unroll
    for (int u = 0; u < 2; u++) {
        int i = tid + (u << 8);
        lrB[u] = i >> 2;
        lcB[u] = (i & 3) << 3;
    }

    uint4 pAH, pAL, pBH[2], pBL[2];
    {
        size_t sa = (size_t)(bm + larA) * K + lcA;
        pAH = *(const uint4*)(AH + sa);
        pAL = *(const uint4*)(AL + sa);
#pragma unroll
        for (int u = 0; u < 2; u++) {
            size_t sb = (size_t)lrB[u] * K + lcB[u];
            pBH[u] = *(const uint4*)(BH + sb);
            pBL[u] = *(const uint4*)(BL + sb);
        }
    }

    const int nchunks = K >> 5;
    for (int c = 0; c < nchunks; c++) {
        *(uint4*)&AsH[larA][lcA] = pAH;
        *(uint4*)&AsL[larA][lcA] = pAL;
#pragma unroll
        for (int u = 0; u < 2; u++) {
            *(uint4*)&BsH[lrB[u]][lcB[u]] = pBH[u];
            *(uint4*)&BsL[lrB[u]][lcB[u]] = pBL[u];
        }
        __syncthreads();

        if (c + 1 < nchunks) {
            const int k0 = (c + 1) << 5;
            size_t sa = (size_t)(bm + larA) * K + k0 + lcA;
            pAH = *(const uint4*)(AH + sa);
            pAL = *(const uint4*)(AL + sa);
#pragma unroll
            for (int u = 0; u < 2; u++) {
                size_t sb = (size_t)lrB[u] * K + k0 + lcB[u];
                pBH[u] = *(const uint4*)(BH + sb);
                pBL[u] = *(const uint4*)(BL + sb);
            }
        }

#pragma unroll
        for (int ks = 0; ks < 2; ks++) {
            wmma::fragment<wmma::matrix_b, 16, 16, 16, __nv_bfloat16, wmma::col_major> bh[2], bl[2];
#pragma unroll
            for (int j = 0; j < 2; j++) {
                wmma::load_matrix_sync(bh[j], &BsH[wn*32 + j*16][ks*16], WLD);
                wmma::load_matrix_sync(bl[j], &BsL[wn*32 + j*16][ks*16], WLD);
            }
#pragma unroll
            for (int i = 0; i < 2; i++) {
                wmma::fragment<wmma::matrix_a, 16, 16, 16, __nv_bfloat16, wmma::row_major> ah, al;
                wmma::load_matrix_sync(ah, &AsH[wm*32 + i*16][ks*16], WLD);
                wmma::load_matrix_sync(al, &AsL[wm*32 + i*16][ks*16], WLD);
#pragma unroll
                for (int j = 0; j < 2; j++) {
                    wmma::mma_sync(acc[i][j], ah, bh[j], acc[i][j]);
                    wmma::mma_sync(acc[i][j], ah, bl[j], acc[i][j]);
                    wmma::mma_sync(acc[i][j], al, bh[j], acc[i][j]);
                }
            }
        }
        __syncthreads();
    }

#pragma unroll
    for (int i = 0; i < 2; i++)
#pragma unroll
        for (int j = 0; j < 2; j++) {
            for (int e = 0; e < acc[i][j].num_elements; e++)
                acc[i][j].x[e] = tanhf(acc[i][j].x[e]);
            wmma::store_matrix_sync(&C[(size_t)(bm + wm*32 + i*16) * 128 + wn*32 + j*16],
                                    acc[i][j], 128, wmma::mem_row_major);
        }
}

/* ================= N=32 variant: BM=64, BN=32, tanh epilogue (XW1) ========= */
__global__ __launch_bounds__(256)
void gemm_wmma3_n32(const __nv_bfloat16* __restrict__ AH, const __nv_bfloat16* __restrict__ AL,
                    const __nv_bfloat16* __restrict__ BH, const __nv_bfloat16* __restrict__ BL,
                    float* __restrict__ C, int M, int K)
{
    __shared__ __nv_bfloat16 AsH[64][WLD];
    __shared__ __nv_bfloat16 AsL[64][WLD];
    __shared__ __nv_bfloat16 BsH[32][WLD];
    __shared__ __nv_bfloat16 BsL[32][WLD];

    const int tid = threadIdx.x;
    const int wid = tid >> 5;
    const int wm = wid >> 1;
    const int wn = wid & 1;
    const int bm = blockIdx.y * 64;

    wmma::fragment<wmma::accumulator, 16, 16, 16, float> acc;
    wmma::fill_fragment(acc, 0.f);

    const int larA = tid >> 2, lcA = (tid & 3) << 3;
    const int lrB = tid >> 2, lcB = (tid & 3) << 3;
    const bool bAct = (tid < 128);

    uint4 pAH, pAL, pBH, pBL;
    {
        size_t sa = (size_t)(bm + larA) * K + lcA;
        pAH = *(const uint4*)(AH + sa);
        pAL = *(const uint4*)(AL + sa);
        if (bAct) {
            size_t sb = (size_t)lrB * K + lcB;
            pBH = *(const uint4*)(BH + sb);
            pBL = *(const uint4*)(BL + sb);
        }
    }

    const int nchunks = K >> 5;
    for (int c = 0; c < nchunks; c++) {
        *(uint4*)&AsH[larA][lcA] = pAH;
        *(uint4*)&AsL[larA][lcA] = pAL;
        if (bAct) {
            *(uint4*)&BsH[lrB][lcB] = pBH;
            *(uint4*)&BsL[lrB][lcB] = pBL;
        }
        __syncthreads();

        if (c + 1 < nchunks) {
            const int k0 = (c + 1) << 5;
            size_t sa = (size_t)(bm + larA) * K + k0 + lcA;
            pAH = *(const uint4*)(AH + sa);
            pAL = *(const uint4*)(AL + sa);
            if (bAct) {
                size_t sb = (size_t)lrB * K + k0 + lcB;
                pBH = *(const uint4*)(BH + sb);
                pBL = *(const uint4*)(BL + sb);
            }
        }

#pragma unroll
        for (int ks = 0; ks < 2; ks++) {
            wmma::fragment<wmma::matrix_b, 16, 16, 16, __nv_bfloat16, wmma::col_major> bh, bl;
            wmma::load_matrix_sync(bh, &BsH[wn*16][ks*16], WLD);
            wmma::load_matrix_sync(bl, &BsL[wn*16][ks*16], WLD);
            wmma::fragment<wmma::matrix_a, 16, 16, 16, __nv_bfloat16, wmma::row_major> ah, al;
            wmma::load_matrix_sync(ah, &AsH[wm*16][ks*16], WLD);
            wmma::load_matrix_sync(al, &AsL[wm*16][ks*16], WLD);
            wmma::mma_sync(acc, ah, bh, acc);
            wmma::mma_sync(acc, ah, bl, acc);
            wmma::mma_sync(acc, al, bh, acc);
        }
        __syncthreads();
    }

    for (int e = 0; e < acc.num_elements; e++)
        acc.x[e] = tanhf(acc.x[e]);
    wmma::store_matrix_sync(&C[(size_t)(bm + wm*16) * 32 + wn*16],
                            acc, 32, wmma::mem_row_major);
}

/* ---------------- fp32 -> bf16 hi/lo split --------------------------------- */
__global__ void split_kernel(const float* __restrict__ in,
                             __nv_bfloat16* __restrict__ hi,
                             __nv_bfloat16* __restrict__ lo, int n4)
{
    int i = blockIdx.x * 256 + threadIdx.x;
    if (i >= n4) return;
    float4 x = ((const float4*)in)[i];
    __nv_bfloat16 h0 = __float2bfloat16(x.x), h1 = __float2bfloat16(x.y);
    __nv_bfloat16 h2 = __float2bfloat16(x.z), h3 = __float2bfloat16(x.w);
    __nv_bfloat162 hA; hA.x = h0; hA.y = h1;
    __nv_bfloat162 hB; hB.x = h2; hB.y = h3;
    __nv_bfloat162 lA; lA.x = __float2bfloat16(x.x - __bfloat162float(h0));
                       lA.y = __float2bfloat16(x.y - __bfloat162float(h1));
    __nv_bfloat162 lB; lB.x = __float2bfloat16(x.z - __bfloat162float(h2));
                       lB.y = __float2bfloat16(x.w - __bfloat162float(h3));
    ((__nv_bfloat162*)hi)[2*i]   = hA;
    ((__nv_bfloat162*)hi)[2*i+1] = hB;
    ((__nv_bfloat162*)lo)[2*i]   = lA;
    ((__nv_bfloat162*)lo)[2*i+1] = lB;
}

/* ---------------- [K,N] fp32 -> [N,K] bf16 hi/lo transpose-split ----------- */
__global__ void tsplit_kernel(const float* __restrict__ in,
                              __nv_bfloat16* __restrict__ hiT,
                              __nv_bfloat16* __restrict__ loT, int K, int N)
{
    int idx = blockIdx.x * 256 + threadIdx.x;
    if (idx >= K * N) return;
    int k = idx / N, n = idx % N;
    float v = in[idx];
    __nv_bfloat16 h = __float2bfloat16(v);
    hiT[(size_t)n * K + k] = h;
    loT[(size_t)n * K + k] = __float2bfloat16(v - __bfloat162float(h));
}

/* ---------------- generic NN GEMM (epi 1,2,3 retained) --------------------- */
__global__ __launch_bounds__(256, 2)
void gemm_nn(const float* __restrict__ A, int lda, int aoff,
             const float* __restrict__ B, int ldb,
             float* __restrict__ C, int ldc,
             int M, int N, int K, int epi, const float* __restrict__ bias,
             const float* __restrict__ Xf, const float* __restrict__ shf,
             const float* __restrict__ tw,
             __nv_bfloat16* __restrict__ CH, __nv_bfloat16* __restrict__ CL)
{
    __shared__ float As[64][36];
    __shared__ float Bs[32][128];
    const int tid = threadIdx.x;
    const int bm = blockIdx.y * 64;
    const int bn = blockIdx.x * 128;
    const int cx = tid & 31;
    const int rg = tid >> 5;

    float4 acc[8];
#pragma unroll
    for (int r = 0; r < 8; r++) acc[r] = make_float4(0.f,0.f,0.f,0.f);

    for (int k0 = 0; k0 < K; k0 += 32) {
#pragma unroll
        for (int u = 0; u < 2; u++) {
            int i = tid + 256*u;
            int r = i >> 3, kq = (i & 7) << 2;
            float4 v = *(const float4*)&A[(size_t)(bm + r) * lda + aoff + k0 + kq];
            *(float4*)&As[r][kq] = v;
        }
#pragma unroll
        for (int u = 0; u < 4; u++) {
            int i = tid + 256*u;
            int kr = i >> 5, nq = (i & 31) << 2;
            float4 v = make_float4(0.f,0.f,0.f,0.f);
            if (bn + nq < N)
                v = *(const float4*)&B[(size_t)(k0 + kr) * ldb + bn + nq];
            *(float4*)&Bs[kr][nq] = v;
        }
        __syncthreads();
#pragma unroll 8
        for (int k = 0; k < 32; k++) {
            float4 bv = *(const float4*)&Bs[k][cx << 2];
#pragma unroll
            for (int r = 0; r < 8; r++) {
                float a = As[rg*8 + r][k];
                acc[r].x = fmaf(a, bv.x, acc[r].x);
                acc[r].y = fmaf(a, bv.y, acc[r].y);
                acc[r].z = fmaf(a, bv.z, acc[r].z);
                acc[r].w = fmaf(a, bv.w, acc[r].w);
            }
        }
        __syncthreads();
    }
    const int n = bn + (cx << 2);
    if (n < N) {
#pragma unroll
        for (int r = 0; r < 8; r++) {
            float4 o = acc[r];
            const int m = bm + rg*8 + r;
            if (epi == 1) {
                o.x = tanhf(o.x); o.y = tanhf(o.y); o.z = tanhf(o.z); o.w = tanhf(o.w);
            } else if (epi == 2) {
                o.x = expf(-expf(bias[n+0] + o.x));
                o.y = expf(-expf(bias[n+1] + o.y));
                o.z = expf(-expf(bias[n+2] + o.z));
                o.w = expf(-expf(bias[n+3] + o.w));
            } else if (epi == 3) {
                const int t = m & (TLEN-1), b = m >> 11;
                float4 x  = *(const float4*)&Xf[(size_t)m * CDIM + n];
                float4 xp = (t == 0)
                    ? *(const float4*)&shf[(size_t)b * CDIM + n]
                    : *(const float4*)&Xf[(size_t)(m-1) * CDIM + n];
                float4 w  = *(const float4*)&tw[n];
                o.x = x.x + (xp.x - x.x) * (w.x + o.x);
                o.y = x.y + (xp.y - x.y) * (w.y + o.y);
                o.z = x.z + (xp.z - x.z) * (w.z + o.z);
                o.w = x.w + (xp.w - x.w) * (w.w + o.w);
                __nv_bfloat16 h0 = __float2bfloat16(o.x), h1 = __float2bfloat16(o.y);
                __nv_bfloat16 h2 = __float2bfloat16(o.z), h3 = __float2bfloat16(o.w);
                __nv_bfloat162 hA; hA.x = h0; hA.y = h1;
                __nv_bfloat162 hB; hB.x = h2; hB.y = h3;
                __nv_bfloat162 lA; lA.x = __float2bfloat16(o.x - __bfloat162float(h0));
                                   lA.y = __float2bfloat16(o.y - __bfloat162float(h1));
                __nv_bfloat162 lB; lB.x = __float2bfloat16(o.z - __bfloat162float(h2));
                                   lB.y = __float2bfloat16(o.w - __bfloat162float(h3));
                ((__nv_bfloat162*)&CH[(size_t)m * ldc + n])[0] = hA;
                ((__nv_bfloat162*)&CH[(size_t)m * ldc + n])[1] = hB;
                ((__nv_bfloat162*)&CL[(size_t)m * ldc + n])[0] = lA;
                ((__nv_bfloat162*)&CL[(size_t)m * ldc + n])[1] = lB;
                continue;
            }
            *(float4*)&C[(size_t)m * ldc + n] = o;
        }
    }
}

/* ================= fused RKVV: one kernel for R, K, V, V2 ==================
   Block tile 32(m) x 64(n). A strip XX1[32][128] and all four maa_w2
   32x64 slices staged in dynamic smem; 4 accumulator sets; single epilogue
   reads x/xp/dec once and writes all four outputs.                       */
#define RK_SMEM (((32*132) + (4*32*64)) * 4)   /* 49664 bytes */

__global__ __launch_bounds__(256)
void rkvv_fused(const float* __restrict__ XX1, const float* __restrict__ W2,
                const float* __restrict__ X, const float* __restrict__ shf,
                const float* __restrict__ DEC,
                const float* __restrict__ tmr, const float* __restrict__ tmk,
                const float* __restrict__ tmv, const float* __restrict__ tmv2,
                const float* __restrict__ trec, const float* __restrict__ tkey,
                float* __restrict__ R, float* __restrict__ K,
                float* __restrict__ V, float* __restrict__ V2)
{
    extern __shared__ float sm[];
    float* As = sm;                    /* [32][132] */
    float* Bs = sm + 32*132;           /* [4][32][64] */

    const int tid = threadIdx.x;
    const int bm = blockIdx.y * 32;
    const int bn = blockIdx.x * 64;

    /* load A strip: 32 rows x 128 cols = 1024 float4, 4/thread */
#pragma unroll
    for (int u = 0; u < 4; u++) {
        int i = tid + (u << 8);
        int r = i >> 5, c = (i & 31) << 2;
        *(float4*)&As[r*132 + c] = *(const float4*)&XX1[(size_t)(bm + r) * 128 + c];
    }
    /* load B: 4 slices x 32 x 64 = 2048 float4-equiv: 512 float4/slice, 2/thread */
#pragma unroll
    for (int f = 0; f < 4; f++) {
#pragma unroll
        for (int u = 0; u < 2; u++) {
            int i = tid + (u << 8);
            int kr = i >> 4, c = (i & 15) << 2;
            *(float4*)&Bs[(f*32 + kr)*64 + c] =
                *(const float4*)&W2[((size_t)f*32 + kr) * CDIM + bn + c];
        }
    }
    __syncthreads();

    const int r  = tid >> 3;           /* 0..31 row       */
    const int cg = (tid & 7) << 3;     /* col offset, 8 f */

    float4 acc[4][2];
#pragma unroll
    for (int f = 0; f < 4; f++) {
        acc[f][0] = make_float4(0.f,0.f,0.f,0.f);
        acc[f][1] = make_float4(0.f,0.f,0.f,0.f);
    }

#pragma unroll
    for (int f = 0; f < 4; f++) {
#pragma unroll 8
        for (int k = 0; k < 32; k++) {
            float a = As[r*132 + f*32 + k];
            float4 b0 = *(const float4*)&Bs[(f*32 + k)*64 + cg];
            float4 b1 = *(const float4*)&Bs[(f*32 + k)*64 + cg + 4];
            acc[f][0].x = fmaf(a, b0.x, acc[f][0].x);
            acc[f][0].y = fmaf(a, b0.y, acc[f][0].y);
            acc[f][0].z = fmaf(a, b0.z, acc[f][0].z);
            acc[f][0].w = fmaf(a, b0.w, acc[f][0].w);
            acc[f][1].x = fmaf(a, b1.x, acc[f][1].x);
            acc[f][1].y = fmaf(a, b1.y, acc[f][1].y);
            acc[f][1].z = fmaf(a, b1.z, acc[f][1].z);
            acc[f][1].w = fmaf(a, b1.w, acc[f][1].w);
        }
    }

    /* epilogue: x/xp/dec read once, four outputs written */
    const int m = bm + r;
    const int t = m & (TLEN-1), b = m >> 11;
#pragma unroll
    for (int h = 0; h < 2; h++) {
        const int n = bn + cg + h*4;
        float4 x  = *(const float4*)&X[(size_t)m * CDIM + n];
        float4 xp = (t == 0)
            ? *(const float4*)&shf[(size_t)b * CDIM + n]
            : *(const float4*)&X[(size_t)(m-1) * CDIM + n];
        float4 d  = *(const float4*)&DEC[(size_t)m * CDIM + n];
        float4 cr = *(const float4*)&tmr[n];
        float4 ck = *(const float4*)&tmk[n];
        float4 cv = *(const float4*)&tmv[n];
        float4 c2 = *(const float4*)&tmv2[n];
        float4 rc = *(const float4*)&trec[n];
        float4 kc = *(const float4*)&tkey[n];
        float4 o_r, o_k, o_v, o_w;
#define RKVV_APPLY(fld) do { \
        float dxv = xp.fld - x.fld; \
        o_r.fld = (x.fld + dxv*(cr.fld + acc[0][h].fld)) * rc.fld; \
        o_k.fld = (x.fld + dxv*(ck.fld + acc[1][h].fld)) * kc.fld * (1.f - d.fld); \
        o_v.fld =  x.fld + dxv*(cv.fld + acc[2][h].fld); \
        o_w.fld =  x.fld + dxv*(c2.fld + acc[3][h].fld); \
} while (0)
        RKVV_APPLY(x); RKVV_APPLY(y); RKVV_APPLY(z); RKVV_APPLY(w);
#undef RKVV_APPLY
        *(float4*)&R [(size_t)m * CDIM + n] = o_r;
        *(float4*)&K [(size_t)m * CDIM + n] = o_k;
        *(float4*)&V [(size_t)m * CDIM + n] = o_v;
        *(float4*)&V2[(size_t)m * CDIM + n] = o_w;
    }
}

/* ---------------- WKV sequential scan, 8-step groups ----------------------- */
#define GSTEP 8
__global__ __launch_bounds__(256, 1)
void wkv_kernel(const float* __restrict__ Rp, const float* __restrict__ Kp,
                const float* __restrict__ Vp, const float* __restrict__ Dp,
                const float* __restrict__ S0, float* __restrict__ Y)
{
    const int bh = blockIdx.x;
    const int b = bh >> 5, h = bh & (NH-1);
    const int tid = threadIdx.x;
    const int j = tid >> 2, iq = tid & 3;

    float S[16];
    const float* s0p = S0 + (size_t)bh * HS * HS;
#pragma unroll
    for (int ii = 0; ii < 16; ii++) S[ii] = s0p[((iq << 4) + ii) * HS + j];

    __shared__ float sbuf[GSTEP][4][64];

    const int grp = tid >> 6, lane = tid & 63;
    const size_t base = ((size_t)b * TLEN) * CDIM + h * HS;
    const float* myp =
        ((grp == 0) ? Rp : (grp == 1) ? Kp : (grp == 2) ? Dp : Vp) + base + lane;

    float pre[GSTEP];
#pragma unroll
    for (int u = 0; u < GSTEP; u++) pre[u] = myp[(size_t)u * CDIM];

    const size_t ybase = base;
    for (int tc = 0; tc < TLEN; tc += GSTEP) {
#pragma unroll
        for (int u = 0; u < GSTEP; u++) sbuf[u][grp][lane] = pre[u];
        __syncthreads();
        if (tc + GSTEP < TLEN) {
#pragma unroll
            for (int u = 0; u < GSTEP; u++)
                pre[u] = myp[(size_t)(tc + GSTEP + u) * CDIM];
        }
#pragma unroll
        for (int u = 0; u < GSTEP; u++) {
            const float4* r4 = (const float4*)sbuf[u][0];
            const float4* k4 = (const float4*)sbuf[u][1];
            const float4* d4 = (const float4*)sbuf[u][2];
            const float vj = sbuf[u][3][j];
            float y = 0.f;
#pragma unroll
            for (int q = 0; q < 4; q++) {
                float4 rv = r4[iq*4 + q];
                y = fmaf(rv.x, S[q*4+0], y);
                y = fmaf(rv.y, S[q*4+1], y);
                y = fmaf(rv.z, S[q*4+2], y);
                y = fmaf(rv.w, S[q*4+3], y);
            }
#pragma unroll
            for (int q = 0; q < 4; q++) {
                float4 dv = d4[iq*4 + q];
                float4 kv = k4[iq*4 + q];
                S[q*4+0] = fmaf(dv.x, S[q*4+0], kv.x * vj);
                S[q*4+1] = fmaf(dv.y, S[q*4+1], kv.y * vj);
                S[q*4+2] = fmaf(dv.z, S[q*4+2], kv.z * vj);
                S[q*4+3] = fmaf(dv.w, S[q*4+3], kv.w * vj);
            }
            y += __shfl_xor_sync(0xffffffffu, y, 1);
            y += __shfl_xor_sync(0xffffffffu, y, 2);
            if (iq == 0) Y[ybase + (size_t)(tc + u) * CDIM + j] = y;
        }
        __syncthreads();
    }
}

/* ---------------- fused add + LayerNorm -> bf16 hi/lo ---------------------- */
__global__ void ln_kernel(const float* __restrict__ Y, const float* __restrict__ V2,
                          const float* __restrict__ gamma, const float* __restrict__ beta,
                          __nv_bfloat16* __restrict__ YH, __nv_bfloat16* __restrict__ YL)
{
    const int m = blockIdx.x;
    const int tid = threadIdx.x;
    const float4* y4 = (const float4*)(Y  + (size_t)m * CDIM);
    const float4* v4 = (const float4*)(V2 + (size_t)m * CDIM);
    float4 vals[2];
    float s = 0.f, s2 = 0.f;
#pragma unroll
    for (int u = 0; u < 2; u++) {
        float4 a = y4[tid + u*256], b = v4[tid + u*256];
        float4 v = make_float4(a.x+b.x, a.y+b.y, a.z+b.z, a.w+b.w);
        vals[u] = v;
        s  += v.x + v.y + v.z + v.w;
        s2 += v.x*v.x + v.y*v.y + v.z*v.z + v.w*v.w;
    }
#pragma unroll
    for (int o = 16; o; o >>= 1) {
        s  += __shfl_xor_sync(0xffffffffu, s,  o);
        s2 += __shfl_xor_sync(0xffffffffu, s2, o);
    }
    __shared__ float sh[2][8];
    const int w = tid >> 5, l = tid & 31;
    if (l == 0) { sh[0][w] = s; sh[1][w] = s2; }
    __syncthreads();
    s = 0.f; s2 = 0.f;
#pragma unroll
    for (int i = 0; i < 8; i++) { s += sh[0][i]; s2 += sh[1][i]; }
    const float mu   = s  * (1.f / CDIM);
    const float var  = s2 * (1.f / CDIM) - mu * mu;
    const float rstd = rsqrtf(var + 1e-5f);
    const float4* g4 = (const float4*)gamma;
    const float4* b4 = (const float4*)beta;
    __nv_bfloat162* yh2 = (__nv_bfloat162*)(YH + (size_t)m * CDIM);
    __nv_bfloat162* yl2 = (__nv_bfloat162*)(YL + (size_t)m * CDIM);
#pragma unroll
    for (int u = 0; u < 2; u++) {
        int c4 = tid + u*256;
        float4 g = g4[c4], bb = b4[c4], v = vals[u];
        float o0 = (v.x - mu) * rstd * g.x + bb.x;
        float o1 = (v.y - mu) * rstd * g.y + bb.y;
        float o2 = (v.z - mu) * rstd * g.z + bb.z;
        float o3 = (v.w - mu) * rstd * g.w + bb.w;
        __nv_bfloat16 h0 = __float2bfloat16(o0), h1 = __float2bfloat16(o1);
        __nv_bfloat16 h2 = __float2bfloat16(o2), h3 = __float2bfloat16(o3);
        __nv_bfloat162 hA; hA.x = h0; hA.y = h1;
        __nv_bfloat162 hB; hB.x = h2; hB.y = h3;
        __nv_bfloat162 lA; lA.x = __float2bfloat16(o0 - __bfloat162float(h0));
                           lA.y = __float2bfloat16(o1 - __bfloat162float(h1));
        __nv_bfloat162 lB; lB.x = __float2bfloat16(o2 - __bfloat162float(h2));
                           lB.y = __float2bfloat16(o3 - __bfloat162float(h3));
        yh2[2*c4]   = hA;  yh2[2*c4+1] = hB;
        yl2[2*c4]   = lA;  yl2[2*c4+1] = lB;
    }
}

/* ---------------- launch --------------------------------------------------- */
extern "C" void kernel_launch(void* const* d_in, const int* in_sizes, int n_in,
                              void* d_out, int out_size)
{
    const float* x_in     = (const float*)d_in[0];
    const float* shiftst  = (const float*)d_in[1];
    const float* wkvstate = (const float*)d_in[2];
    const float* tmr      = (const float*)d_in[3];
    const float* tmk      = (const float*)d_in[4];
    const float* tmv      = (const float*)d_in[5];
    const float* tmv2     = (const float*)d_in[6];
    const float* maa_w1   = (const float*)d_in[7];
    const float* maa_w2   = (const float*)d_in[8];
    const float* tmw      = (const float*)d_in[9];
    const float* ww1      = (const float*)d_in[10];
    const float* ww2      = (const float*)d_in[11];
    const float* tdecay   = (const float*)d_in[12];
    const float* dw1      = (const float*)d_in[13];
    const float* dw2      = (const float*)d_in[14];
    /* d_in[15] = time_faaaa: unused (u == 0 in this model) */
    const float* trec     = (const float*)d_in[16];
    const float* tkey     = (const float*)d_in[17];
    const float* value_w  = (const float*)d_in[18];
    const float* output_w = (const float*)d_in[19];
    const float* gamma    = (const float*)d_in[20];
    const float* beta     = (const float*)d_in[21];
    float* out = (float*)d_out;

    float *pX, *pXX1, *pXW1, *pT1, *pDEC, *pR, *pK, *pV, *pV2, *pY;
    __nv_bfloat16 *pXIH, *pXIL, *pXH, *pXL, *pYH, *pYL, *pXWH, *pXWL;
    __nv_bfloat16 *pVWH, *pVWL, *pOWH, *pOWL;
    __nv_bfloat16 *pW1TH, *pW1TL, *pDW1TH, *pDW1TL, *pWW1TH, *pWW1TL;
    cudaGetSymbolAddress((void**)&pX,   g_X);
    cudaGetSymbolAddress((void**)&pXX1, g_XX1);
    cudaGetSymbolAddress((void**)&pXW1, g_XW1);
    cudaGetSymbolAddress((void**)&pT1,  g_T1);
    cudaGetSymbolAddress((void**)&pDEC, g_DEC);
    cudaGetSymbolAddress((void**)&pR,   g_R);
    cudaGetSymbolAddress((void**)&pK,   g_K);
    cudaGetSymbolAddress((void**)&pV,   g_V);
    cudaGetSymbolAddress((void**)&pV2,  g_V2);
    cudaGetSymbolAddress((void**)&pY,   g_Y);
    cudaGetSymbolAddress((void**)&pXIH, g_XIH);
    cudaGetSymbolAddress((void**)&pXIL, g_XIL);
    cudaGetSymbolAddress((void**)&pXH,  g_XH);
    cudaGetSymbolAddress((void**)&pXL,  g_XL);
    cudaGetSymbolAddress((void**)&pYH,  g_YH);
    cudaGetSymbolAddress((void**)&pYL,  g_YL);
    cudaGetSymbolAddress((void**)&pXWH, g_XWH);
    cudaGetSymbolAddress((void**)&pXWL, g_XWL);
    cudaGetSymbolAddress((void**)&pVWH, g_VWH);
    cudaGetSymbolAddress((void**)&pVWL, g_VWL);
    cudaGetSymbolAddress((void**)&pOWH, g_OWH);
    cudaGetSymbolAddress((void**)&pOWL, g_OWL);
    cudaGetSymbolAddress((void**)&pW1TH,  g_W1TH);
    cudaGetSymbolAddress((void**)&pW1TL,  g_W1TL);
    cudaGetSymbolAddress((void**)&pDW1TH, g_DW1TH);
    cudaGetSymbolAddress((void**)&pDW1TL, g_DW1TL);
    cudaGetSymbolAddress((void**)&pWW1TH, g_WW1TH);
    cudaGetSymbolAddress((void**)&pWW1TL, g_WW1TL);

    cudaFuncSetAttribute(rkvv_fused,
                         cudaFuncAttributeMaxDynamicSharedMemorySize, RK_SMEM);

    const size_t SZ = (size_t)MTOT * CDIM;
    const int SPLIT_BLK_X  = (int)(SZ / 4 / 256);
    const int SPLIT_BLK_W  = (int)((size_t)CDIM * CDIM / 4 / 256);
    const int TS_BLKS128 = (CDIM * 128 + 255) / 256;
    const int TS_BLKS32  = (CDIM * 32 + 255) / 256;
    const float* NUL = (const float*)0;
    __nv_bfloat16* NB = (__nv_bfloat16*)0;

    /* splits */
    split_kernel<<<SPLIT_BLK_X, 256>>>(x_in, pXIH, pXIL, (int)(SZ / 4));
    split_kernel<<<SPLIT_BLK_W, 256>>>(value_w,  pVWH, pVWL, (int)((size_t)CDIM*CDIM/4));
    split_kernel<<<SPLIT_BLK_W, 256>>>(output_w, pOWH, pOWL, (int)((size_t)CDIM*CDIM/4));
    tsplit_kernel<<<TS_BLKS128, 256>>>(maa_w1, pW1TH, pW1TL, CDIM, 128);
    tsplit_kernel<<<TS_BLKS128, 256>>>(dw1,    pDW1TH, pDW1TL, CDIM, 128);
    tsplit_kernel<<<TS_BLKS32,  256>>>(ww1,    pWW1TH, pWW1TL, CDIM, 32);

    /* XX1 = tanh(x_in @ maa_w1)  (skinny wmma) */
    gemm_wmma3_skinny<<<dim3(1, MTOT/64), 256>>>(pXIH, pXIL, pW1TH, pW1TL, pXX1,
                                                 MTOT, CDIM);
    /* X = x_in @ value_w^T */
    gemm_wmma3<<<dim3(CDIM/128, MTOT/128), 256>>>(pXIH, pXIL, pVWH, pVWL, pX,
                                                  MTOT, CDIM, CDIM);
    /* XH/XL = split(X) */
    split_kernel<<<SPLIT_BLK_X, 256>>>(pX, pXH, pXL, (int)(SZ / 4));
    /* XW1 = tanh(X @ w_w1)  (N=32 wmma) */
    gemm_wmma3_n32<<<dim3(1, MTOT/64), 256>>>(pXH, pXL, pWW1TH, pWW1TL, pXW1,
                                              MTOT, CDIM);
    /* XW = X + dxprev*(time_maa_w + XW1 @ w_w2) -> bf16 hi/lo (epi=3) */
    gemm_nn<<<dim3(CDIM/128, MTOT/64), 256>>>(pXW1, 32, 0, ww2, CDIM, (float*)0, CDIM,
                                              MTOT, CDIM, 32, 3, NUL,
                                              pX, shiftst, tmw, pXWH, pXWL);
    /* T1 = tanh(XW @ decay_w1)  (skinny wmma) */
    gemm_wmma3_skinny<<<dim3(1, MTOT/64), 256>>>(pXWH, pXWL, pDW1TH, pDW1TL, pT1,
                                                 MTOT, CDIM);
    /* DEC = exp(-exp(time_decay + T1 @ decay_w2)) */
    gemm_nn<<<dim3(CDIM/128, MTOT/64), 256>>>(pT1, 128, 0, dw2, CDIM, pDEC, CDIM,
                                              MTOT, CDIM, 128, 2, tdecay, NUL, NUL, NUL, NB, NB);
    /* fused RKVV: one kernel, four outputs */
    rkvv_fused<<<dim3(CDIM/64, MTOT/32), 256, RK_SMEM>>>(
        pXX1, maa_w2, pX, shiftst, pDEC,
        tmr, tmk, tmv, tmv2, trec, tkey,
        pR, pK, pV, pV2);
    /* WKV scan (8-step groups) */
    wkv_kernel<<<BATCH*NH, 256>>>(pR, pK, pV, pDEC, wkvstate, pY);
    /* yn = LN(y + v2) -> bf16 hi/lo */
    ln_kernel<<<MTOT, 256>>>(pY, pV2, gamma, beta, pYH, pYL);
    /* out = yn @ output_w^T */
    gemm_wmma3<<<dim3(CDIM/128, MTOT/128), 256>>>(pYH, pYL, pOWH, pOWL, out,
                                                  MTOT, CDIM, CDIM);
}